// round 2
// baseline (speedup 1.0000x reference)
#include <cuda_runtime.h>
#include <math.h>

constexpr int Bn   = 64;
constexpr int Hn   = 512;
constexpr int Wn   = 512;
constexpr int NPTS = 512;
constexpr int HWn  = Hn * Wn;
constexpr int SLICES = 16;                 // reduce blocks per image
constexpr int RB = Bn * SLICES;            // 1024 reduce blocks
constexpr int NTAP = Bn * NPTS * 9;        // 294912 point-taps
constexpr int TB = NTAP / 256;             // 1152 tap blocks
constexpr float SCALE = 0.25f;             // 512/2048
constexpr double CELL_AREA = 16.0;

// Static scratch (zero-initialized; restored each call for graph replay)
__device__ float  g_target[(size_t)Bn * HWn];
__device__ double g_S[Bn], g_Q[Bn], g_T[Bn], g_A[Bn], g_C[Bn];
__device__ unsigned g_done;

__device__ __forceinline__ float wgt_of(int r2) {
    return r2 == 0 ? 1.0f : (r2 == 1 ? 0.60653066f : 0.49306869f);
}

// Decode (point-tap index) -> image b, cell index (or -1 if invalid), weight
__device__ __forceinline__ void tap_decode(const float* __restrict__ points,
                                           int u, int& b, int& idx, float& w) {
    int pt  = u / 9;
    int tap = u - pt * 9;
    b = pt >> 9;                                   // /NPTS
    float px = points[2 * pt + 0];
    float py = points[2 * pt + 1];
    int x = (int)fminf(fmaxf(px * SCALE, 0.f), (float)(Wn - 1));
    int y = (int)fminf(fmaxf(py * SCALE, 0.f), (float)(Hn - 1));
    int dy = tap / 3 - 1, dx = tap - (tap / 3) * 3 - 1;
    int ny = y + dy, nx = x + dx;
    if ((unsigned)ny < (unsigned)Hn && (unsigned)nx < (unsigned)Wn) {
        idx = b * HWn + ny * Wn + nx;
        w = wgt_of(dy * dy + dx * dx);
    } else { idx = -1; w = 0.f; }
}

// Launch 1: blocks [0,RB) stream-reduce pred (S,Q); blocks [RB,RB+TB) splat
// target and gather A = sum w*pred[cell] (independent of target).
__global__ void k_main(const float* __restrict__ pred,
                       const float* __restrict__ points) {
    if (blockIdx.x < RB) {
        int b = blockIdx.x >> 4, slice = blockIdx.x & (SLICES - 1);
        constexpr int CH = HWn / 4 / SLICES;       // 4096 float4 per block
        const float4* p = reinterpret_cast<const float4*>(pred)
                          + (size_t)b * (HWn / 4) + (size_t)slice * CH;
        float s = 0.f, q = 0.f;
        #pragma unroll 4
        for (int i = threadIdx.x; i < CH; i += blockDim.x) {
            float4 v = p[i];
            s += (v.x + v.y) + (v.z + v.w);
            q += v.x * v.x + v.y * v.y + v.z * v.z + v.w * v.w;
        }
        #pragma unroll
        for (int o = 16; o; o >>= 1) {
            s += __shfl_down_sync(0xffffffffu, s, o);
            q += __shfl_down_sync(0xffffffffu, q, o);
        }
        __shared__ float ss[8], sq[8];
        int lane = threadIdx.x & 31, wid = threadIdx.x >> 5;
        if (lane == 0) { ss[wid] = s; sq[wid] = q; }
        __syncthreads();
        if (wid == 0) {
            s = (lane < 8) ? ss[lane] : 0.f;
            q = (lane < 8) ? sq[lane] : 0.f;
            #pragma unroll
            for (int o = 4; o; o >>= 1) {
                s += __shfl_down_sync(0xffffffffu, s, o);
                q += __shfl_down_sync(0xffffffffu, q, o);
            }
            if (lane == 0) {
                atomicAdd(&g_S[b], (double)s);
                atomicAdd(&g_Q[b], (double)q);
            }
        }
    } else {
        int u = (blockIdx.x - RB) * 256 + threadIdx.x;   // < NTAP
        int b, idx; float w;
        tap_decode(points, u, b, idx, w);
        float a = 0.f;
        if (idx >= 0) {
            atomicAdd(&g_target[idx], w);
            a = w * __ldg(&pred[idx]);
        }
        // 4608 taps per image => warps never straddle images
        float ws = w;
        #pragma unroll
        for (int o = 16; o; o >>= 1) {
            ws += __shfl_down_sync(0xffffffffu, ws, o);
            a  += __shfl_down_sync(0xffffffffu, a, o);
        }
        if ((threadIdx.x & 31) == 0) {
            atomicAdd(&g_T[b], (double)ws);
            atomicAdd(&g_A[b], (double)a);
        }
    }
}

// Launch 2: C = sum_cell t^2 via atomicExch (gather + clean in one pass),
// then the last block finalizes and resets all accumulators for replay.
__global__ void k_tail(float* __restrict__ out) {
    int u = blockIdx.x * 256 + threadIdx.x;
    {
        // points cached from k_main? No — recompute from global points ptr
        // passed via constant? We need points here; see note: stored pointer.
    }
    // -- real body in k_tail2 (kept single kernel via param) --
    out = out; u = u;
}

__global__ void k_tail2(const float* __restrict__ points,
                        float* __restrict__ out) {
    int u = blockIdx.x * 256 + threadIdx.x;
    int b, idx; float w;
    tap_decode(points, u, b, idx, w);
    float c = 0.f;
    if (idx >= 0) {
        float v = atomicExch(&g_target[idx], 0.f);   // read + clean
        c = v * v;                                   // exactly one winner per cell
    }
    #pragma unroll
    for (int o = 16; o; o >>= 1) c += __shfl_down_sync(0xffffffffu, c, o);
    if ((threadIdx.x & 31) == 0) atomicAdd(&g_C[b], (double)c);

    // last-block-done: finalize + reset
    __shared__ int is_last;
    __threadfence();
    __syncthreads();
    if (threadIdx.x == 0) {
        unsigned r = atomicAdd(&g_done, 1u);
        is_last = (r == gridDim.x - 1) ? 1 : 0;
    }
    __syncthreads();
    if (!is_last) return;

    int t = threadIdx.x;
    double cnt = 0.0, sp = 0.0;
    if (t < Bn) {
        double S = g_S[t];
        cnt = fabs(S / CELL_AREA - (double)NPTS);
        double Sp = S + 1e-8;
        double T = g_T[t];
        sp = (g_Q[t] / (Sp * Sp) - 2.0 * g_A[t] / (Sp * T) + g_C[t] / (T * T))
             / (double)HWn;
        g_S[t] = 0.0; g_Q[t] = 0.0; g_T[t] = 0.0; g_A[t] = 0.0; g_C[t] = 0.0;
    }
    #pragma unroll
    for (int o = 16; o; o >>= 1) {
        cnt += __shfl_down_sync(0xffffffffu, cnt, o);
        sp  += __shfl_down_sync(0xffffffffu, sp, o);
    }
    __shared__ double sc[2], ssp[2];
    int lane = threadIdx.x & 31, wid = threadIdx.x >> 5;
    if (wid < 2 && lane == 0) { sc[wid] = cnt; ssp[wid] = sp; }
    __syncthreads();
    if (threadIdx.x == 0) {
        g_done = 0u;
        double count_loss = (sc[0] + sc[1]) / (double)Bn;
        double spatial    = (ssp[0] + ssp[1]) / (double)Bn;
        out[0] = (float)(2.5 * count_loss + 0.1 * spatial);
        out[1] = (float)count_loss;
        out[2] = (float)spatial;
    }
}

extern "C" void kernel_launch(void* const* d_in, const int* in_sizes, int n_in,
                              void* d_out, int out_size) {
    const float* pred   = (const float*)d_in[0];
    const float* points = (const float*)d_in[1];
    float* out = (float*)d_out;

    k_main<<<RB + TB, 256>>>(pred, points);
    k_tail2<<<TB, 256>>>(points, out);
}